// round 3
// baseline (speedup 1.0000x reference)
#include <cuda_runtime.h>
#include <math.h>

#define BATCH 4
#define TSTEPS 8
#define HC 64
#define HW 4096
#define CHW (HC*HW)            // 262144
#define NB (BATCH*HC*HW)       // 1048576

typedef unsigned long long u64;

// ---------------- f32x2 packed helpers ----------------
__device__ __forceinline__ u64 pk2(float lo, float hi){
  u64 r; asm("mov.b64 %0, {%1,%2};" : "=l"(r) : "f"(lo), "f"(hi)); return r;
}
__device__ __forceinline__ void fma2(u64 &acc, u64 a, u64 b){
  asm("fma.rn.f32x2 %0, %1, %2, %0;" : "+l"(acc) : "l"(a), "l"(b));
}
__device__ __forceinline__ float2 upk(u64 v){
  float2 f; asm("mov.b64 {%0,%1}, %2;" : "=f"(f.x), "=f"(f.y) : "l"(v)); return f;
}

// ---------------- device scratch (static) ----------------
__device__ float g_h0[NB];
__device__ float g_c0[NB];
__device__ float g_c1[NB];
__device__ float g_m[NB];
__device__ float g_A[BATCH*192*HW];
__device__ float g_Bm[BATCH*128*HW];
__device__ float g_rc[NB], g_xm[NB];
__device__ float g_r[NB], g_z[NB], g_o[NB], g_xr[NB], g_xz[NB];
__device__ float g_gcr[NB], g_gmr[NB], g_gct[NB], g_gmt[NB];
__device__ float g_q[NB], g_k[NB];
__device__ float g_attn[BATCH*64*64];
__device__ float g_hs[BATCH*TSTEPS*HC*HW];
__device__ float g_zero[NB];   // NEVER written -> stays zero

__device__ __forceinline__ float sigf(float x){ return 1.f/(1.f+expf(-x)); }

__global__ void tg_zero_states(){
  int i = blockIdx.x*256 + threadIdx.x;
  if (i < NB){ g_h0[i]=0.f; g_c0[i]=0.f; g_c1[i]=0.f; g_m[i]=0.f; }
}

// ---------------- dual-input 3x3 conv, f32x2 packed ----------------
// Block 128 thr = (16 rows x 8 col-groups). Each thread: 8 px x 8 oc.
// cin processed in chunks of 4; weights duplicated-packed in smem.
#define CC 4
#define TILE_E 1188   // 18*66 per cin
__global__ void __launch_bounds__(128) tg_conv3x3(
    const float* __restrict__ in0, int C0, long bs0,
    const float* __restrict__ in1, int C1, long bs1,
    const float* __restrict__ w, const float* __restrict__ bias,
    float* __restrict__ out, long bsOut)
{
  __shared__ float tile[CC][18*68];
  __shared__ u64   ws2[CC][72];
  const int tid = threadIdx.x;
  const int b   = blockIdx.z;
  const int ocb = blockIdx.y;        // group of 8 out channels
  const int y0  = blockIdx.x * 16;   // 16 rows per block
  const int ty  = tid >> 3;          // 0..15
  const int tx  = (tid & 7) * 8;     // 0..56
  const int Cin = C0 + C1;

  u64 acc[8][4];
#pragma unroll
  for (int oc=0;oc<8;oc++){
    float bv = bias[ocb*8+oc];
    u64 bb = pk2(bv,bv);
#pragma unroll
    for (int p=0;p<4;p++) acc[oc][p] = bb;
  }

  for (int cc0=0; cc0<Cin; cc0+=CC){
    __syncthreads();
    // cooperative tile load: CC cins x 18 rows x 66 cols (halo)
    for (int idx=tid; idx<CC*TILE_E; idx+=128){
      int ci  = idx / TILE_E;
      int rem = idx - ci*TILE_E;
      int r   = rem / 66;
      int c   = rem - r*66;
      int gy = y0 - 1 + r, gx = c - 1;
      int cing = cc0 + ci;
      const float* src = (cing < C0) ? in0 + (long)b*bs0 + (long)cing*HW
                                     : in1 + (long)b*bs1 + (long)(cing-C0)*HW;
      float v = (gy>=0 && gy<64 && gx>=0 && gx<64) ? src[gy*64+gx] : 0.f;
      tile[ci][r*68 + c] = v;
    }
    // weights: CC cins x 8 oc x 9, duplicated into both f32x2 halves
    for (int i=tid; i<CC*72; i+=128){
      int ci  = i / 72;
      int rem = i - ci*72;
      int oc  = rem/9, k = rem - oc*9;
      float v = w[((long)(ocb*8+oc)*Cin + cc0+ci)*9 + k];
      ws2[ci][rem] = pk2(v,v);
    }
    __syncthreads();

#pragma unroll
    for (int ci=0; ci<CC; ci++){
      float v[3][10];
#pragma unroll
      for (int r=0;r<3;r++)
#pragma unroll
        for (int c=0;c<10;c++)
          v[r][c] = tile[ci][(ty+r)*68 + tx + c];
      u64 pk[3][9];
#pragma unroll
      for (int r=0;r<3;r++)
#pragma unroll
        for (int c=0;c<9;c++)
          pk[r][c] = pk2(v[r][c], v[r][c+1]);
#pragma unroll
      for (int oc=0;oc<8;oc++){
        u64 wv[9];
#pragma unroll
        for (int k=0;k<9;k++) wv[k] = ws2[ci][oc*9+k];
#pragma unroll
        for (int p=0;p<4;p++)
#pragma unroll
          for (int ky=0;ky<3;ky++)
#pragma unroll
            for (int kx=0;kx<3;kx++)
              fma2(acc[oc][p], wv[ky*3+kx], pk[ky][2*p+kx]);
      }
    }
  }

  const long ob = (long)b*bsOut + (long)(ocb*8)*HW + (long)(y0+ty)*64 + tx;
#pragma unroll
  for (int oc=0;oc<8;oc++){
#pragma unroll
    for (int p=0;p<4;p++){
      float2 f = upk(acc[oc][p]);
      *reinterpret_cast<float2*>(&out[ob + (long)oc*HW + 2*p]) = f;
    }
  }
}

// ---------------- gate pointwise ----------------
__global__ void tg_gates(
    const float* __restrict__ A, const float* __restrict__ Bm,
    const float* __restrict__ h, long hbs,
    const float* __restrict__ c,
    const float* __restrict__ tg, const float* __restrict__ tdh,
    const float* __restrict__ tdm)
{
  int idx = blockIdx.x*256 + threadIdx.x;
  if (idx >= NB) return;
  int pix = idx & (HW-1);
  int ch  = (idx >> 12) & 63;
  int b   = idx >> 18;
  float gate = sigf(tg[ch]);
  float dh = expf(-tdh[ch]);
  float dm = expf(-tdm[ch]);
  long aB = ((long)b*192 + ch)*HW + pix;
  long bB = ((long)b*128 + ch)*HW + pix;
  float hv = h[(long)b*hbs + (long)ch*HW + pix];
  float cv = c[idx];
  float mv = g_m[idx];
  float r  = sigf(A[aB]*gate + hv*dh);
  float z  = sigf(A[aB + (long)64*HW]*gate + hv*dh);
  float o  = sigf(A[aB + (long)128*HW]);
  float xr = sigf(Bm[bB]*gate + mv*dm);
  float xz = sigf(Bm[bB + (long)64*HW]*gate + mv*dm);
  g_r[idx]=r; g_z[idx]=z; g_o[idx]=o; g_xr[idx]=xr; g_xz[idx]=xz;
  g_rc[idx]=r*cv; g_xm[idx]=xr*mv;
}

// ---------------- cell update ----------------
__global__ void tg_cm(float* __restrict__ c)
{
  int idx = blockIdx.x*256 + threadIdx.x;
  if (idx >= NB) return;
  float tc = tanhf(g_gcr[idx]);
  float tm = tanhf(g_gmr[idx]);
  float zv = g_z[idx], xzv = g_xz[idx];
  c[idx]   = zv*c[idx]   + (1.f-zv)*tc;
  g_m[idx] = xzv*g_m[idx] + (1.f-xzv)*tm;
  g_gct[idx]=tc; g_gmt[idx]=tm;
}

// ---------------- 1x1 conv (f32x2) with fused h = o*tanh(.) ----------------
// Block 128 thr, each thread 4 px x 16 oc. grid (8, BATCH, 4)
__global__ void __launch_bounds__(128) tg_conv1x1(
    const float* __restrict__ c,
    const float* __restrict__ w, const float* __restrict__ bias,
    float* __restrict__ out, long bsOut)
{
  __shared__ u64 ws[16*128];
  const int tid = threadIdx.x;
  const int b   = blockIdx.y;
  const int ocg = blockIdx.z;   // group of 16 oc
  for (int i=tid;i<16*128;i+=128){
    float v = w[(long)(ocg*16)*128 + i];
    ws[i] = pk2(v,v);
  }
  __syncthreads();
  const int pix = (blockIdx.x*128 + tid)*4;
  u64 acc[16][2];
#pragma unroll
  for (int oc=0;oc<16;oc++){
    float bv = bias[ocg*16+oc];
    acc[oc][0] = pk2(bv,bv); acc[oc][1] = acc[oc][0];
  }
  const long base = (long)b*CHW + pix;
  for (int cc=0;cc<64;cc++){
    const float* pc = &c[base + (long)cc*HW];
    u64 v0 = *reinterpret_cast<const u64*>(pc);
    u64 v1 = *reinterpret_cast<const u64*>(pc+2);
#pragma unroll
    for (int oc=0;oc<16;oc++){
      u64 wv = ws[oc*128+cc];
      fma2(acc[oc][0], wv, v0);
      fma2(acc[oc][1], wv, v1);
    }
  }
  for (int cc=0;cc<64;cc++){
    const float* pm = &g_m[base + (long)cc*HW];
    u64 v0 = *reinterpret_cast<const u64*>(pm);
    u64 v1 = *reinterpret_cast<const u64*>(pm+2);
#pragma unroll
    for (int oc=0;oc<16;oc++){
      u64 wv = ws[oc*128+64+cc];
      fma2(acc[oc][0], wv, v0);
      fma2(acc[oc][1], wv, v1);
    }
  }
#pragma unroll
  for (int oc=0;oc<16;oc++){
    int ocf = ocg*16+oc;
    const float* po = &g_o[base + (long)ocf*HW];
    float4 ov = *reinterpret_cast<const float4*>(po);
    float2 a0 = upk(acc[oc][0]);
    float2 a1 = upk(acc[oc][1]);
    float4 res;
    res.x = ov.x * tanhf(a0.x);
    res.y = ov.y * tanhf(a0.y);
    res.z = ov.z * tanhf(a1.x);
    res.w = ov.w * tanhf(a1.y);
    *reinterpret_cast<float4*>(&out[(long)b*bsOut + (long)ocf*HW + pix]) = res;
  }
}

// ---------------- q/k from final-step last-layer gates ----------------
__global__ void tg_qk()
{
  int idx = blockIdx.x*256 + threadIdx.x;
  if (idx >= NB) return;
  float rv = g_r[idx], xrv = g_xr[idx];
  g_q[idx] = 0.25f*(rv + xrv + g_c1[idx] + g_gct[idx]);
  g_k[idx] = 0.25f*(rv + xrv + g_m[idx]  + g_gmt[idx]);
}

// ---------------- attention logits + softmax ----------------
__global__ void tg_attn()
{
  __shared__ float qs[HW];
  __shared__ float red[2];
  __shared__ float logits[64];
  __shared__ float tmp[64];
  const int b = blockIdx.y, i = blockIdx.x, t = threadIdx.x;  // 64 threads
  const float* qrow = g_q + ((long)b*64 + i)*HW;
  for (int n=t;n<HW;n+=64) qs[n] = qrow[n];
  __syncthreads();
  for (int j=0;j<64;j++){
    const float* krow = g_k + ((long)b*64 + j)*HW;
    float s = 0.f;
    for (int n=t;n<HW;n+=64) s += qs[n]*krow[n];
#pragma unroll
    for (int off=16;off;off>>=1) s += __shfl_down_sync(0xffffffffu, s, off);
    if ((t&31)==0) red[t>>5] = s;
    __syncthreads();
    if (t==0) logits[j] = (red[0]+red[1]) * 0.015625f;
    __syncthreads();
  }
  float xv = logits[t];
  tmp[t] = xv; __syncthreads();
  for (int s2=32; s2; s2>>=1){ if (t<s2) tmp[t] = fmaxf(tmp[t], tmp[t+s2]); __syncthreads(); }
  float mx = tmp[0]; __syncthreads();
  float e = expf(xv - mx);
  tmp[t] = e; __syncthreads();
  for (int s2=32; s2; s2>>=1){ if (t<s2) tmp[t] += tmp[t+s2]; __syncthreads(); }
  g_attn[((long)b*64+i)*64 + t] = e / tmp[0];
}

// ---------------- apply attention ----------------
__global__ void __launch_bounds__(256) tg_apply(float* __restrict__ out)
{
  __shared__ float as[64*64];
  const int b = blockIdx.z, tt = blockIdx.y;
  const int n = blockIdx.x*256 + threadIdx.x;
  for (int i=threadIdx.x;i<4096;i+=256) as[i] = g_attn[(long)b*4096 + i];
  __syncthreads();
  float acc[64];
#pragma unroll
  for (int c=0;c<64;c++) acc[c]=0.f;
  const float* v = g_hs + (((long)b*TSTEPS + tt)*64)*HW + n;
  for (int d=0; d<64; d++){
    float vv = v[(long)d*HW];
#pragma unroll
    for (int c=0;c<64;c++) acc[c] += as[c*64+d]*vv;
  }
  float* op = out + (((long)b*TSTEPS + tt)*64)*HW + n;
#pragma unroll
  for (int c=0;c<64;c++) op[(long)c*HW] = acc[c];
}

// ---------------- orchestration ----------------
extern "C" void kernel_launch(void* const* d_in, const int* in_sizes, int n_in,
                              void* d_out, int out_size)
{
  (void)in_sizes; (void)n_in; (void)out_size;
  const float* x      = (const float*)d_in[0];
  const float* w_rzo0 = (const float*)d_in[1];
  const float* b_rzo0 = (const float*)d_in[2];
  const float* w_rz0  = (const float*)d_in[3];
  const float* b_rz0  = (const float*)d_in[4];
  const float* w_h0   = (const float*)d_in[5];
  const float* b_h0   = (const float*)d_in[6];
  const float* w_o0   = (const float*)d_in[7];
  const float* b_o0   = (const float*)d_in[8];
  const float* td_h0  = (const float*)d_in[9];
  const float* td_m0  = (const float*)d_in[10];
  const float* tg0    = (const float*)d_in[11];
  const float* w_rzo1 = (const float*)d_in[12];
  const float* b_rzo1 = (const float*)d_in[13];
  const float* w_rz1  = (const float*)d_in[14];
  const float* b_rz1  = (const float*)d_in[15];
  const float* w_h1   = (const float*)d_in[16];
  const float* b_h1   = (const float*)d_in[17];
  const float* w_o1   = (const float*)d_in[18];
  const float* b_o1   = (const float*)d_in[19];
  const float* td_h1  = (const float*)d_in[20];
  const float* td_m1  = (const float*)d_in[21];
  const float* tg1    = (const float*)d_in[22];

  float *p_h0,*p_c0,*p_c1,*p_m,*p_A,*p_Bm,*p_rc,*p_xm,*p_gcr,*p_gmr,*p_hs,*p_zero;
  cudaGetSymbolAddress((void**)&p_h0,  g_h0);
  cudaGetSymbolAddress((void**)&p_c0,  g_c0);
  cudaGetSymbolAddress((void**)&p_c1,  g_c1);
  cudaGetSymbolAddress((void**)&p_m,   g_m);
  cudaGetSymbolAddress((void**)&p_A,   g_A);
  cudaGetSymbolAddress((void**)&p_Bm,  g_Bm);
  cudaGetSymbolAddress((void**)&p_rc,  g_rc);
  cudaGetSymbolAddress((void**)&p_xm,  g_xm);
  cudaGetSymbolAddress((void**)&p_gcr, g_gcr);
  cudaGetSymbolAddress((void**)&p_gmr, g_gmr);
  cudaGetSymbolAddress((void**)&p_hs,  g_hs);
  cudaGetSymbolAddress((void**)&p_zero,g_zero);

  const long nbs = (long)CHW;

  tg_zero_states<<<NB/256, 256>>>();

  for (int t=0; t<TSTEPS; t++){
    // ---------- layer 0 (Cin = 16+64 = 80) ----------
    const float* xt = x + (long)t*16*HW;
    const long xbs = (long)TSTEPS*16*HW;
    tg_conv3x3<<<dim3(4,24,BATCH),128>>>(xt,16,xbs, p_h0,64,nbs, w_rzo0,b_rzo0, p_A, (long)192*HW);
    tg_conv3x3<<<dim3(4,16,BATCH),128>>>(xt,16,xbs, p_m ,64,nbs, w_rz0 ,b_rz0 , p_Bm,(long)128*HW);
    tg_gates<<<NB/256,256>>>(p_A,p_Bm, p_h0,nbs, p_c0, tg0, td_h0, td_m0);
    tg_conv3x3<<<dim3(4, 8,BATCH),128>>>(xt,16,xbs, p_rc,64,nbs, w_h0,b_h0, p_gcr, nbs);
    tg_conv3x3<<<dim3(4, 8,BATCH),128>>>(xt,16,xbs, p_xm,64,nbs, w_h0,b_h0, p_gmr, nbs);
    tg_cm<<<NB/256,256>>>(p_c0);
    tg_conv1x1<<<dim3(8,BATCH,4),128>>>(p_c0, w_o0, b_o0, p_h0, nbs);

    // ---------- layer 1 (Cin = 64+64 = 128) ----------
    const float* h1p = (t==0) ? p_zero : (p_hs + (long)(t-1)*CHW);
    const long h1bs  = (t==0) ? nbs : (long)TSTEPS*CHW;
    tg_conv3x3<<<dim3(4,24,BATCH),128>>>(p_h0,64,nbs, h1p,64,h1bs, w_rzo1,b_rzo1, p_A, (long)192*HW);
    tg_conv3x3<<<dim3(4,16,BATCH),128>>>(p_h0,64,nbs, p_m,64,nbs,  w_rz1 ,b_rz1 , p_Bm,(long)128*HW);
    tg_gates<<<NB/256,256>>>(p_A,p_Bm, h1p,h1bs, p_c1, tg1, td_h1, td_m1);
    tg_conv3x3<<<dim3(4, 8,BATCH),128>>>(p_h0,64,nbs, p_rc,64,nbs, w_h1,b_h1, p_gcr, nbs);
    tg_conv3x3<<<dim3(4, 8,BATCH),128>>>(p_h0,64,nbs, p_xm,64,nbs, w_h1,b_h1, p_gmr, nbs);
    tg_cm<<<NB/256,256>>>(p_c1);
    tg_conv1x1<<<dim3(8,BATCH,4),128>>>(p_c1, w_o1, b_o1, p_hs + (long)t*CHW, (long)TSTEPS*CHW);
  }

  tg_qk<<<NB/256,256>>>();
  tg_attn<<<dim3(64,BATCH),64>>>();
  tg_apply<<<dim3(16,TSTEPS,BATCH),256>>>((float*)d_out);
}

// round 4
// speedup vs baseline: 1.3285x; 1.3285x over previous
#include <cuda_runtime.h>
#include <math.h>

#define BATCH 4
#define TSTEPS 8
#define HC 64
#define HW 4096
#define CHW (HC*HW)            // 262144
#define NB (BATCH*HC*HW)       // 1048576

typedef unsigned long long u64;

// ---------------- f32x2 packed helpers ----------------
__device__ __forceinline__ u64 pk2(float lo, float hi){
  u64 r; asm("mov.b64 %0, {%1,%2};" : "=l"(r) : "f"(lo), "f"(hi)); return r;
}
__device__ __forceinline__ void fma2(u64 &acc, u64 a, u64 b){
  asm("fma.rn.f32x2 %0, %1, %2, %0;" : "+l"(acc) : "l"(a), "l"(b));
}
__device__ __forceinline__ float2 upk(u64 v){
  float2 f; asm("mov.b64 {%0,%1}, %2;" : "=f"(f.x), "=f"(f.y) : "l"(v)); return f;
}

// ---------------- device scratch (static) ----------------
__device__ float g_h0[NB];
__device__ float g_c0[NB];
__device__ float g_c1[NB];
__device__ float g_m[NB];
__device__ float g_A[BATCH*192*HW];
__device__ float g_Bm[BATCH*128*HW];
__device__ float g_rc[NB], g_xm[NB];
__device__ float g_r[NB], g_z[NB], g_o[NB], g_xr[NB], g_xz[NB];
__device__ float g_gcr[NB], g_gmr[NB], g_gct[NB], g_gmt[NB];
__device__ float g_q[NB], g_k[NB];
__device__ float g_attn[BATCH*64*64];
__device__ float g_hs[BATCH*TSTEPS*HC*HW];
__device__ float g_zero[NB];   // NEVER written -> stays zero

__device__ __forceinline__ float sigf(float x){ return 1.f/(1.f+expf(-x)); }

__global__ void tg_zero_states(){
  int i = blockIdx.x*256 + threadIdx.x;
  if (i < NB){ g_h0[i]=0.f; g_c0[i]=0.f; g_c1[i]=0.f; g_m[i]=0.f; }
}

// ---------------- merged dual-stream 3x3 conv, f32x2 packed ----------------
// Two independent convs sharing in0 merged into one grid: blocks with
// blockIdx.y < nA8 compute stream A (in1A,wA,outA), the rest stream B.
// Block 256 thr = (16 rows x 16 col-groups of 4px). Each thread: 4 px x 8 oc.
#define CC 4
#define TILE_E 1188   // 18*66 per cin
__global__ void __launch_bounds__(256) tg_conv3x3(
    const float* __restrict__ in0, int C0, long bs0,
    const float* __restrict__ in1A, long bs1A,
    const float* __restrict__ in1B, long bs1B,
    const float* __restrict__ wA, const float* __restrict__ bA,
    float* __restrict__ outA, long bsOutA,
    const float* __restrict__ wB, const float* __restrict__ bB,
    float* __restrict__ outB, long bsOutB,
    int nA8)
{
  __shared__ float tile[CC][18*68];
  __shared__ u64   ws2[CC][72];
  const int tid = threadIdx.x;
  const int b   = blockIdx.z;
  int ocb = blockIdx.y;
  const int y0  = blockIdx.x * 16;
  const int ty  = tid >> 4;          // 0..15
  const int tx  = (tid & 15) * 4;    // 0..60
  const int Cin = C0 + 64;

  const float* in1; const float* w; const float* bias;
  float* out; long bs1, bsOut;
  if (ocb < nA8){ in1=in1A; bs1=bs1A; w=wA; bias=bA; out=outA; bsOut=bsOutA; }
  else { ocb-=nA8; in1=in1B; bs1=bs1B; w=wB; bias=bB; out=outB; bsOut=bsOutB; }

  u64 acc[8][2];
#pragma unroll
  for (int oc=0;oc<8;oc++){
    float bv = bias[ocb*8+oc];
    u64 bb = pk2(bv,bv);
    acc[oc][0] = bb; acc[oc][1] = bb;
  }

  for (int cc0=0; cc0<Cin; cc0+=CC){
    __syncthreads();
    // cooperative tile load: CC cins x 18 rows x 66 cols (halo)
    for (int idx=tid; idx<CC*TILE_E; idx+=256){
      int ci  = idx / TILE_E;
      int rem = idx - ci*TILE_E;
      int r   = rem / 66;
      int c   = rem - r*66;
      int gy = y0 - 1 + r, gx = c - 1;
      int cing = cc0 + ci;
      const float* src = (cing < C0) ? in0 + (long)b*bs0 + (long)cing*HW
                                     : in1 + (long)b*bs1 + (long)(cing-C0)*HW;
      float v = (gy>=0 && gy<64 && gx>=0 && gx<64) ? src[gy*64+gx] : 0.f;
      tile[ci][r*68 + c] = v;
    }
    // weights: CC cins x 8 oc x 9, duplicated into both f32x2 halves
    for (int i=tid; i<CC*72; i+=256){
      int ci  = i / 72;
      int rem = i - ci*72;
      int oc  = rem/9, k = rem - oc*9;
      float v = w[((long)(ocb*8+oc)*Cin + cc0+ci)*9 + k];
      ws2[ci][rem] = pk2(v,v);
    }
    __syncthreads();

#pragma unroll
    for (int ci=0; ci<CC; ci++){
      float v[3][6];
#pragma unroll
      for (int r=0;r<3;r++)
#pragma unroll
        for (int c=0;c<6;c++)
          v[r][c] = tile[ci][(ty+r)*68 + tx + c];
      u64 pk[3][5];
#pragma unroll
      for (int r=0;r<3;r++)
#pragma unroll
        for (int c=0;c<5;c++)
          pk[r][c] = pk2(v[r][c], v[r][c+1]);
#pragma unroll
      for (int oc=0;oc<8;oc++){
        u64 wv[9];
#pragma unroll
        for (int k=0;k<9;k++) wv[k] = ws2[ci][oc*9+k];
#pragma unroll
        for (int p=0;p<2;p++)
#pragma unroll
          for (int ky=0;ky<3;ky++)
#pragma unroll
            for (int kx=0;kx<3;kx++)
              fma2(acc[oc][p], wv[ky*3+kx], pk[ky][2*p+kx]);
      }
    }
  }

  const long ob = (long)b*bsOut + (long)(ocb*8)*HW + (long)(y0+ty)*64 + tx;
#pragma unroll
  for (int oc=0;oc<8;oc++){
    float2 f0 = upk(acc[oc][0]);
    float2 f1 = upk(acc[oc][1]);
    float4 res = make_float4(f0.x,f0.y,f1.x,f1.y);
    *reinterpret_cast<float4*>(&out[ob + (long)oc*HW]) = res;
  }
}

// ---------------- gate pointwise ----------------
__global__ void tg_gates(
    const float* __restrict__ A, const float* __restrict__ Bm,
    const float* __restrict__ h, long hbs,
    const float* __restrict__ c,
    const float* __restrict__ tg, const float* __restrict__ tdh,
    const float* __restrict__ tdm)
{
  int idx = blockIdx.x*256 + threadIdx.x;
  if (idx >= NB) return;
  int pix = idx & (HW-1);
  int ch  = (idx >> 12) & 63;
  int b   = idx >> 18;
  float gate = sigf(tg[ch]);
  float dh = expf(-tdh[ch]);
  float dm = expf(-tdm[ch]);
  long aB = ((long)b*192 + ch)*HW + pix;
  long bB = ((long)b*128 + ch)*HW + pix;
  float hv = h[(long)b*hbs + (long)ch*HW + pix];
  float cv = c[idx];
  float mv = g_m[idx];
  float r  = sigf(A[aB]*gate + hv*dh);
  float z  = sigf(A[aB + (long)64*HW]*gate + hv*dh);
  float o  = sigf(A[aB + (long)128*HW]);
  float xr = sigf(Bm[bB]*gate + mv*dm);
  float xz = sigf(Bm[bB + (long)64*HW]*gate + mv*dm);
  g_r[idx]=r; g_z[idx]=z; g_o[idx]=o; g_xr[idx]=xr; g_xz[idx]=xz;
  g_rc[idx]=r*cv; g_xm[idx]=xr*mv;
}

// ---------------- cell update ----------------
__global__ void tg_cm(float* __restrict__ c)
{
  int idx = blockIdx.x*256 + threadIdx.x;
  if (idx >= NB) return;
  float tc = tanhf(g_gcr[idx]);
  float tm = tanhf(g_gmr[idx]);
  float zv = g_z[idx], xzv = g_xz[idx];
  c[idx]   = zv*c[idx]   + (1.f-zv)*tc;
  g_m[idx] = xzv*g_m[idx] + (1.f-xzv)*tm;
  g_gct[idx]=tc; g_gmt[idx]=tm;
}

// ---------------- 1x1 conv (f32x2) with fused h = o*tanh(.) ----------------
// Block 256 thr, each thread 2 px x 4 oc. grid (8, BATCH, 16)
__global__ void __launch_bounds__(256) tg_conv1x1(
    const float* __restrict__ c,
    const float* __restrict__ w, const float* __restrict__ bias,
    float* __restrict__ out, long bsOut)
{
  __shared__ u64 ws[4*128];
  const int tid = threadIdx.x;
  const int b   = blockIdx.y;
  const int ocg = blockIdx.z;   // group of 4 oc
  for (int i=tid;i<4*128;i+=256){
    float v = w[(long)(ocg*4)*128 + i];
    ws[i] = pk2(v,v);
  }
  __syncthreads();
  const int pix = (blockIdx.x*256 + tid)*2;
  u64 acc[4];
#pragma unroll
  for (int oc=0;oc<4;oc++){
    float bv = bias[ocg*4+oc];
    acc[oc] = pk2(bv,bv);
  }
  const long base = (long)b*CHW + pix;
  for (int cc=0;cc<64;cc++){
    u64 v0 = *reinterpret_cast<const u64*>(&c[base + (long)cc*HW]);
#pragma unroll
    for (int oc=0;oc<4;oc++) fma2(acc[oc], ws[oc*128+cc], v0);
  }
  for (int cc=0;cc<64;cc++){
    u64 v0 = *reinterpret_cast<const u64*>(&g_m[base + (long)cc*HW]);
#pragma unroll
    for (int oc=0;oc<4;oc++) fma2(acc[oc], ws[oc*128+64+cc], v0);
  }
#pragma unroll
  for (int oc=0;oc<4;oc++){
    int ocf = ocg*4+oc;
    float2 ov = *reinterpret_cast<const float2*>(&g_o[base + (long)ocf*HW]);
    float2 a = upk(acc[oc]);
    float2 res;
    res.x = ov.x * tanhf(a.x);
    res.y = ov.y * tanhf(a.y);
    *reinterpret_cast<float2*>(&out[(long)b*bsOut + (long)ocf*HW + pix]) = res;
  }
}

// ---------------- q/k from final-step last-layer gates ----------------
__global__ void tg_qk()
{
  int idx = blockIdx.x*256 + threadIdx.x;
  if (idx >= NB) return;
  float rv = g_r[idx], xrv = g_xr[idx];
  g_q[idx] = 0.25f*(rv + xrv + g_c1[idx] + g_gct[idx]);
  g_k[idx] = 0.25f*(rv + xrv + g_m[idx]  + g_gmt[idx]);
}

// ---------------- attention logits + softmax ----------------
__global__ void tg_attn()
{
  __shared__ float qs[HW];
  __shared__ float red[2];
  __shared__ float logits[64];
  __shared__ float tmp[64];
  const int b = blockIdx.y, i = blockIdx.x, t = threadIdx.x;  // 64 threads
  const float* qrow = g_q + ((long)b*64 + i)*HW;
  for (int n=t;n<HW;n+=64) qs[n] = qrow[n];
  __syncthreads();
  for (int j=0;j<64;j++){
    const float* krow = g_k + ((long)b*64 + j)*HW;
    float s = 0.f;
    for (int n=t;n<HW;n+=64) s += qs[n]*krow[n];
#pragma unroll
    for (int off=16;off;off>>=1) s += __shfl_down_sync(0xffffffffu, s, off);
    if ((t&31)==0) red[t>>5] = s;
    __syncthreads();
    if (t==0) logits[j] = (red[0]+red[1]) * 0.015625f;
    __syncthreads();
  }
  float xv = logits[t];
  tmp[t] = xv; __syncthreads();
  for (int s2=32; s2; s2>>=1){ if (t<s2) tmp[t] = fmaxf(tmp[t], tmp[t+s2]); __syncthreads(); }
  float mx = tmp[0]; __syncthreads();
  float e = expf(xv - mx);
  tmp[t] = e; __syncthreads();
  for (int s2=32; s2; s2>>=1){ if (t<s2) tmp[t] += tmp[t+s2]; __syncthreads(); }
  g_attn[((long)b*64+i)*64 + t] = e / tmp[0];
}

// ---------------- apply attention ----------------
__global__ void __launch_bounds__(256) tg_apply(float* __restrict__ out)
{
  __shared__ float as[64*64];
  const int b = blockIdx.z, tt = blockIdx.y;
  const int n = blockIdx.x*256 + threadIdx.x;
  for (int i=threadIdx.x;i<4096;i+=256) as[i] = g_attn[(long)b*4096 + i];
  __syncthreads();
  float acc[64];
#pragma unroll
  for (int c=0;c<64;c++) acc[c]=0.f;
  const float* v = g_hs + (((long)b*TSTEPS + tt)*64)*HW + n;
  for (int d=0; d<64; d++){
    float vv = v[(long)d*HW];
#pragma unroll
    for (int c=0;c<64;c++) acc[c] += as[c*64+d]*vv;
  }
  float* op = out + (((long)b*TSTEPS + tt)*64)*HW + n;
#pragma unroll
  for (int c=0;c<64;c++) op[(long)c*HW] = acc[c];
}

// ---------------- orchestration ----------------
extern "C" void kernel_launch(void* const* d_in, const int* in_sizes, int n_in,
                              void* d_out, int out_size)
{
  (void)in_sizes; (void)n_in; (void)out_size;
  const float* x      = (const float*)d_in[0];
  const float* w_rzo0 = (const float*)d_in[1];
  const float* b_rzo0 = (const float*)d_in[2];
  const float* w_rz0  = (const float*)d_in[3];
  const float* b_rz0  = (const float*)d_in[4];
  const float* w_h0   = (const float*)d_in[5];
  const float* b_h0   = (const float*)d_in[6];
  const float* w_o0   = (const float*)d_in[7];
  const float* b_o0   = (const float*)d_in[8];
  const float* td_h0  = (const float*)d_in[9];
  const float* td_m0  = (const float*)d_in[10];
  const float* tg0    = (const float*)d_in[11];
  const float* w_rzo1 = (const float*)d_in[12];
  const float* b_rzo1 = (const float*)d_in[13];
  const float* w_rz1  = (const float*)d_in[14];
  const float* b_rz1  = (const float*)d_in[15];
  const float* w_h1   = (const float*)d_in[16];
  const float* b_h1   = (const float*)d_in[17];
  const float* w_o1   = (const float*)d_in[18];
  const float* b_o1   = (const float*)d_in[19];
  const float* td_h1  = (const float*)d_in[20];
  const float* td_m1  = (const float*)d_in[21];
  const float* tg1    = (const float*)d_in[22];

  float *p_h0,*p_c0,*p_c1,*p_m,*p_A,*p_Bm,*p_rc,*p_xm,*p_gcr,*p_gmr,*p_hs,*p_zero;
  cudaGetSymbolAddress((void**)&p_h0,  g_h0);
  cudaGetSymbolAddress((void**)&p_c0,  g_c0);
  cudaGetSymbolAddress((void**)&p_c1,  g_c1);
  cudaGetSymbolAddress((void**)&p_m,   g_m);
  cudaGetSymbolAddress((void**)&p_A,   g_A);
  cudaGetSymbolAddress((void**)&p_Bm,  g_Bm);
  cudaGetSymbolAddress((void**)&p_rc,  g_rc);
  cudaGetSymbolAddress((void**)&p_xm,  g_xm);
  cudaGetSymbolAddress((void**)&p_gcr, g_gcr);
  cudaGetSymbolAddress((void**)&p_gmr, g_gmr);
  cudaGetSymbolAddress((void**)&p_hs,  g_hs);
  cudaGetSymbolAddress((void**)&p_zero,g_zero);

  const long nbs = (long)CHW;

  tg_zero_states<<<NB/256, 256>>>();

  for (int t=0; t<TSTEPS; t++){
    // ---------- layer 0 (Cin = 16+64 = 80) ----------
    const float* xt = x + (long)t*16*HW;
    const long xbs = (long)TSTEPS*16*HW;
    // merged A(192oc, in1=h) + B(128oc, in1=m): 24 + 16 = 40 oc-groups
    tg_conv3x3<<<dim3(4,40,BATCH),256>>>(xt,16,xbs, p_h0,nbs, p_m,nbs,
        w_rzo0,b_rzo0,p_A,(long)192*HW, w_rz0,b_rz0,p_Bm,(long)128*HW, 24);
    tg_gates<<<NB/256,256>>>(p_A,p_Bm, p_h0,nbs, p_c0, tg0, td_h0, td_m0);
    // merged gc(in1=rc) + gm(in1=xm), same weights w_h0: 8 + 8 groups
    tg_conv3x3<<<dim3(4,16,BATCH),256>>>(xt,16,xbs, p_rc,nbs, p_xm,nbs,
        w_h0,b_h0,p_gcr,nbs, w_h0,b_h0,p_gmr,nbs, 8);
    tg_cm<<<NB/256,256>>>(p_c0);
    tg_conv1x1<<<dim3(8,BATCH,16),256>>>(p_c0, w_o0, b_o0, p_h0, nbs);

    // ---------- layer 1 (Cin = 64+64 = 128) ----------
    const float* h1p = (t==0) ? p_zero : (p_hs + (long)(t-1)*CHW);
    const long h1bs  = (t==0) ? nbs : (long)TSTEPS*CHW;
    tg_conv3x3<<<dim3(4,40,BATCH),256>>>(p_h0,64,nbs, h1p,h1bs, p_m,nbs,
        w_rzo1,b_rzo1,p_A,(long)192*HW, w_rz1,b_rz1,p_Bm,(long)128*HW, 24);
    tg_gates<<<NB/256,256>>>(p_A,p_Bm, h1p,h1bs, p_c1, tg1, td_h1, td_m1);
    tg_conv3x3<<<dim3(4,16,BATCH),256>>>(p_h0,64,nbs, p_rc,nbs, p_xm,nbs,
        w_h1,b_h1,p_gcr,nbs, w_h1,b_h1,p_gmr,nbs, 8);
    tg_cm<<<NB/256,256>>>(p_c1);
    tg_conv1x1<<<dim3(8,BATCH,16),256>>>(p_c1, w_o1, b_o1, p_hs + (long)t*CHW, (long)TSTEPS*CHW);
  }

  tg_qk<<<NB/256,256>>>();
  tg_attn<<<dim3(64,BATCH),64>>>();
  tg_apply<<<dim3(16,TSTEPS,BATCH),256>>>((float*)d_out);
}

// round 5
// speedup vs baseline: 2.0276x; 1.5263x over previous
#include <cuda_runtime.h>
#include <math.h>
#include <stdint.h>

#define BATCH 4
#define TSTEPS 8
#define HC 64
#define HW 4096
#define CHW (HC*HW)            // 262144
#define NB (BATCH*HC*HW)       // 1048576

typedef unsigned long long u64;

// ---------------- f32x2 packed helpers ----------------
__device__ __forceinline__ u64 pk2(float lo, float hi){
  u64 r; asm("mov.b64 %0, {%1,%2};" : "=l"(r) : "f"(lo), "f"(hi)); return r;
}
__device__ __forceinline__ u64 dup2(float v){
  u64 r; asm("mov.b64 %0, {%1,%1};" : "=l"(r) : "f"(v)); return r;
}
__device__ __forceinline__ void fma2(u64 &acc, u64 a, u64 b){
  asm("fma.rn.f32x2 %0, %1, %2, %0;" : "+l"(acc) : "l"(a), "l"(b));
}
__device__ __forceinline__ float2 upk(u64 v){
  float2 f; asm("mov.b64 {%0,%1}, %2;" : "=f"(f.x), "=f"(f.y) : "l"(v)); return f;
}
// ---------------- cp.async helpers ----------------
__device__ __forceinline__ void cpa4(uint32_t saddr, const float* g, int nbytes){
  asm volatile("cp.async.ca.shared.global [%0], [%1], 4, %2;"
               :: "r"(saddr), "l"(g), "r"(nbytes) : "memory");
}
__device__ __forceinline__ void cpcommit(){ asm volatile("cp.async.commit_group;" ::: "memory"); }
__device__ __forceinline__ void cpwait1(){ asm volatile("cp.async.wait_group 1;" ::: "memory"); }
__device__ __forceinline__ void cpwait0(){ asm volatile("cp.async.wait_group 0;" ::: "memory"); }

// ---------------- device scratch (static) ----------------
__device__ float g_h0[NB];
__device__ float g_c0[NB];
__device__ float g_c1[NB];
__device__ float g_m[NB];
__device__ float g_A[BATCH*192*HW];
__device__ float g_Bm[BATCH*128*HW];
__device__ float g_rc[NB], g_xm[NB];
__device__ float g_r[NB], g_z[NB], g_o[NB], g_xr[NB], g_xz[NB];
__device__ float g_gcr[NB], g_gmr[NB], g_gct[NB], g_gmt[NB];
__device__ float g_q[NB], g_k[NB];
__device__ float g_attn[BATCH*64*64];
__device__ float g_hs[BATCH*TSTEPS*HC*HW];
__device__ float g_zero[NB];   // NEVER written -> stays zero

__device__ __forceinline__ float sigf(float x){ return 1.f/(1.f+expf(-x)); }

__global__ void tg_zero_states(){
  int i = blockIdx.x*256 + threadIdx.x;
  if (i < NB){ g_h0[i]=0.f; g_c0[i]=0.f; g_c1[i]=0.f; g_m[i]=0.f; }
}

// ---------------- merged dual-stream 3x3 conv, oc-pair f32x2, cp.async pipelined --------
// Block 128 thr = 8 rows x 16 colgroups(4px). Each thread: 4 px x 8 oc (4 oc-pairs).
// Block covers 8 rows x 64 cols x 8 oc. Grid y selects stream A vs B (< nA8 -> A).
// nUnits y-tile units per block (y0 = (bx + u*xStride)*8).
// cin pipeline: chunks of CC=4 cins, 3-buffer tile (cp.async, zfill halo),
// 2-buffer pair-packed weights, ONE __syncthreads per chunk.
#define CC 4
__global__ void __launch_bounds__(128,5) tg_conv3x3(
    const float* __restrict__ in0, int C0, long bs0,
    const float* __restrict__ in1A, long bs1A,
    const float* __restrict__ in1B, long bs1B,
    const float* __restrict__ wA, const float* __restrict__ bA,
    float* __restrict__ outA, long bsOutA,
    const float* __restrict__ wB, const float* __restrict__ bB,
    float* __restrict__ outB, long bsOutB,
    int nA8, int Cin, int nUnits, int xStride)
{
  __shared__ __align__(16) float tile[3][CC][720];   // 10 rows x 72 cols, px0 at col 4
  __shared__ __align__(16) u64   ws[2][CC][4][12];   // [pair][ky][kx(pad4)] oc-pair packed

  const int tid = threadIdx.x;
  const int b   = blockIdx.z;
  int ocb = blockIdx.y;
  const int ty = tid >> 4;          // 0..7
  const int tx = (tid & 15) * 4;    // 0..60

  const float* in1; const float* w; const float* bias;
  float* out; long bs1, bsOut;
  if (ocb < nA8){ in1=in1A; bs1=bs1A; w=wA; bias=bA; out=outA; bsOut=bsOutA; }
  else { ocb-=nA8; in1=in1B; bs1=bs1B; w=wB; bias=bB; out=outB; bsOut=bsOutB; }

  const float* pin0 = in0 + (long)b*bs0;
  const float* pin1 = in1 + (long)b*bs1;

  // weight slot descriptors (144 u64 per chunk, 2 slots/thread)
  int wex[2], woff[2], wsts[2];
#pragma unroll
  for (int s=0;s<2;s++){
    int j = tid + s*128;
    wex[s] = (j < 144);
    int jj = wex[s] ? j : 0;
    int ci = jj/36; int rem = jj - ci*36; int p = rem/9; int k = rem - p*9;
    int oc0 = ocb*8 + 2*p;
    woff[s] = (oc0*Cin + ci)*9 + k;
    wsts[s] = (((ci*4)+p)*12 + (k/3)*4 + (k%3))*8;  // byte offset within one ws buffer
  }
  const int nch = Cin/CC;
  const int wsBufBytes = CC*4*12*8;  // 1536
  char* wsb = (char*)&ws[0][0][0][0];
  uint32_t tbase = (uint32_t)__cvta_generic_to_shared(&tile[0][0][0]);

  u64 bb[4];
#pragma unroll
  for (int p=0;p<4;p++) bb[p] = pk2(bias[ocb*8+2*p], bias[ocb*8+2*p+1]);

  for (int u=0; u<nUnits; u++){
    const int y0 = (blockIdx.x + u*xStride)*8;

    // tile slot descriptors for this unit (6 slots covering 660 elems/cin)
    int soff[6];   // smem byte offset within one cin tile
    int genc[6];   // >=0: gmem offset; -1: zfill; -2: skip
#pragma unroll
    for (int i=0;i<6;i++){
      int idx = tid + i*128;
      int ex = (idx < 660);
      int ii = ex ? idx : 0;
      int r = ii/66, c = ii - r*66;
      soff[i] = (r*72 + c + 3)*4;
      int gy = y0 + r - 1, gx = c - 1;
      int ok = ex && (gx>=0) && (gx<64) && (gy>=0) && (gy<64);
      genc[i] = ok ? (gy*64 + gx) : (ex ? -1 : -2);
    }

    u64 acc[4][4];
#pragma unroll
    for (int p=0;p<4;p++)
#pragma unroll
      for (int px=0;px<4;px++) acc[p][px] = bb[p];

    // ---- prologue ----
    float wh[2][2];
#pragma unroll
    for (int s=0;s<2;s++) if (wex[s]){   // chunk 0 weights: LDG + STS now
      float a0 = w[woff[s]];
      float a1 = w[woff[s] + Cin*9];
      *(u64*)(wsb + wsts[s]) = pk2(a0, a1);
    }
#pragma unroll
    for (int s=0;s<2;s++) if (wex[s]){   // chunk 1 weights: LDG, hold
      wh[s][0] = w[woff[s] + 9*CC];
      wh[s][1] = w[woff[s] + 9*CC + Cin*9];
    }
    // tile chunks 0 and 1
#pragma unroll 1
    for (int cc=0; cc<2; cc++){
#pragma unroll
      for (int ci=0;ci<CC;ci++){
        int cing = cc*CC + ci;
        const float* src = (cing < C0) ? pin0 + (long)cing*HW
                                       : pin1 + (long)(cing-C0)*HW;
        uint32_t sb = tbase + (uint32_t)((cc*CC + ci)*720*4);
#pragma unroll
        for (int i=0;i<6;i++)
          if (genc[i] != -2)
            cpa4(sb + soff[i], src + (genc[i]>=0 ? genc[i] : 0), genc[i]>=0 ? 4 : 0);
      }
      cpcommit();
    }

    // ---- main pipeline ----
    for (int c=0; c<nch; c++){
      if (c+1 < nch) cpwait1(); else cpwait0();
      __syncthreads();
      if (c+1 < nch){
#pragma unroll
        for (int s=0;s<2;s++) if (wex[s])
          *(u64*)(wsb + ((c+1)&1)*wsBufBytes + wsts[s]) = pk2(wh[s][0], wh[s][1]);
      }
      if (c+2 < nch){
#pragma unroll
        for (int s=0;s<2;s++) if (wex[s]){
          wh[s][0] = w[woff[s] + (c+2)*9*CC];
          wh[s][1] = w[woff[s] + (c+2)*9*CC + Cin*9];
        }
        int buf = (c+2)%3;
#pragma unroll
        for (int ci=0;ci<CC;ci++){
          int cing = (c+2)*CC + ci;
          const float* src = (cing < C0) ? pin0 + (long)cing*HW
                                         : pin1 + (long)(cing-C0)*HW;
          uint32_t sb = tbase + (uint32_t)((buf*CC + ci)*720*4);
#pragma unroll
          for (int i=0;i<6;i++)
            if (genc[i] != -2)
              cpa4(sb + soff[i], src + (genc[i]>=0 ? genc[i] : 0), genc[i]>=0 ? 4 : 0);
        }
        cpcommit();
      }
      // compute chunk c
      const int tb = c%3, wb = c&1;
#pragma unroll
      for (int ci=0;ci<CC;ci++){
#pragma unroll
        for (int r=0;r<3;r++){
          const float* row = &tile[tb][ci][(ty+r)*72 + tx + 3];
          float v0 = row[0];
          float4 vm = *reinterpret_cast<const float4*>(row+1);
          float v5 = row[5];
          u64 pv0=dup2(v0), pv1=dup2(vm.x), pv2=dup2(vm.y),
              pv3=dup2(vm.z), pv4=dup2(vm.w), pv5=dup2(v5);
#pragma unroll
          for (int p=0;p<4;p++){
            ulonglong2 w01 = *reinterpret_cast<const ulonglong2*>(&ws[wb][ci][p][r*4]);
            u64 w2 = ws[wb][ci][p][r*4+2];
            fma2(acc[p][0], w01.x, pv0); fma2(acc[p][0], w01.y, pv1); fma2(acc[p][0], w2, pv2);
            fma2(acc[p][1], w01.x, pv1); fma2(acc[p][1], w01.y, pv2); fma2(acc[p][1], w2, pv3);
            fma2(acc[p][2], w01.x, pv2); fma2(acc[p][2], w01.y, pv3); fma2(acc[p][2], w2, pv4);
            fma2(acc[p][3], w01.x, pv3); fma2(acc[p][3], w01.y, pv4); fma2(acc[p][3], w2, pv5);
          }
        }
      }
    }

    // ---- epilogue: unpack oc-pairs, store ----
    const long ob = (long)b*bsOut + (long)(ocb*8)*HW + (long)(y0+ty)*64 + tx;
#pragma unroll
    for (int p=0;p<4;p++){
      float2 a0=upk(acc[p][0]), a1=upk(acc[p][1]), a2=upk(acc[p][2]), a3=upk(acc[p][3]);
      float4 lo = make_float4(a0.x,a1.x,a2.x,a3.x);
      float4 hi = make_float4(a0.y,a1.y,a2.y,a3.y);
      *reinterpret_cast<float4*>(&out[ob + (long)(2*p  )*HW]) = lo;
      *reinterpret_cast<float4*>(&out[ob + (long)(2*p+1)*HW]) = hi;
    }
    __syncthreads();  // protect smem before next unit's prologue
  }
}

// ---------------- gate pointwise ----------------
__global__ void tg_gates(
    const float* __restrict__ A, const float* __restrict__ Bm,
    const float* __restrict__ h, long hbs,
    const float* __restrict__ c,
    const float* __restrict__ tg, const float* __restrict__ tdh,
    const float* __restrict__ tdm)
{
  int idx = blockIdx.x*256 + threadIdx.x;
  if (idx >= NB) return;
  int pix = idx & (HW-1);
  int ch  = (idx >> 12) & 63;
  int b   = idx >> 18;
  float gate = sigf(tg[ch]);
  float dh = expf(-tdh[ch]);
  float dm = expf(-tdm[ch]);
  long aB = ((long)b*192 + ch)*HW + pix;
  long bB = ((long)b*128 + ch)*HW + pix;
  float hv = h[(long)b*hbs + (long)ch*HW + pix];
  float cv = c[idx];
  float mv = g_m[idx];
  float r  = sigf(A[aB]*gate + hv*dh);
  float z  = sigf(A[aB + (long)64*HW]*gate + hv*dh);
  float o  = sigf(A[aB + (long)128*HW]);
  float xr = sigf(Bm[bB]*gate + mv*dm);
  float xz = sigf(Bm[bB + (long)64*HW]*gate + mv*dm);
  g_r[idx]=r; g_z[idx]=z; g_o[idx]=o; g_xr[idx]=xr; g_xz[idx]=xz;
  g_rc[idx]=r*cv; g_xm[idx]=xr*mv;
}

// ---------------- cell update ----------------
__global__ void tg_cm(float* __restrict__ c)
{
  int idx = blockIdx.x*256 + threadIdx.x;
  if (idx >= NB) return;
  float tc = tanhf(g_gcr[idx]);
  float tm = tanhf(g_gmr[idx]);
  float zv = g_z[idx], xzv = g_xz[idx];
  c[idx]   = zv*c[idx]   + (1.f-zv)*tc;
  g_m[idx] = xzv*g_m[idx] + (1.f-xzv)*tm;
  g_gct[idx]=tc; g_gmt[idx]=tm;
}

// ---------------- 1x1 conv (f32x2) with fused h = o*tanh(.) ----------------
__global__ void __launch_bounds__(256) tg_conv1x1(
    const float* __restrict__ c,
    const float* __restrict__ w, const float* __restrict__ bias,
    float* __restrict__ out, long bsOut)
{
  __shared__ u64 ws[4*128];
  const int tid = threadIdx.x;
  const int b   = blockIdx.y;
  const int ocg = blockIdx.z;   // group of 4 oc
  for (int i=tid;i<4*128;i+=256){
    float v = w[(long)(ocg*4)*128 + i];
    ws[i] = pk2(v,v);
  }
  __syncthreads();
  const int pix = (blockIdx.x*256 + tid)*2;
  u64 acc[4];
#pragma unroll
  for (int oc=0;oc<4;oc++){
    float bv = bias[ocg*4+oc];
    acc[oc] = pk2(bv,bv);
  }
  const long base = (long)b*CHW + pix;
  for (int cc=0;cc<64;cc++){
    u64 v0 = *reinterpret_cast<const u64*>(&c[base + (long)cc*HW]);
#pragma unroll
    for (int oc=0;oc<4;oc++) fma2(acc[oc], ws[oc*128+cc], v0);
  }
  for (int cc=0;cc<64;cc++){
    u64 v0 = *reinterpret_cast<const u64*>(&g_m[base + (long)cc*HW]);
#pragma unroll
    for (int oc=0;oc<4;oc++) fma2(acc[oc], ws[oc*128+64+cc], v0);
  }
#pragma unroll
  for (int oc=0;oc<4;oc++){
    int ocf = ocg*4+oc;
    float2 ov = *reinterpret_cast<const float2*>(&g_o[base + (long)ocf*HW]);
    float2 a = upk(acc[oc]);
    float2 res;
    res.x = ov.x * tanhf(a.x);
    res.y = ov.y * tanhf(a.y);
    *reinterpret_cast<float2*>(&out[(long)b*bsOut + (long)ocf*HW + pix]) = res;
  }
}

// ---------------- q/k from final-step last-layer gates ----------------
__global__ void tg_qk()
{
  int idx = blockIdx.x*256 + threadIdx.x;
  if (idx >= NB) return;
  float rv = g_r[idx], xrv = g_xr[idx];
  g_q[idx] = 0.25f*(rv + xrv + g_c1[idx] + g_gct[idx]);
  g_k[idx] = 0.25f*(rv + xrv + g_m[idx]  + g_gmt[idx]);
}

// ---------------- attention logits + softmax ----------------
__global__ void tg_attn()
{
  __shared__ float qs[HW];
  __shared__ float red[2];
  __shared__ float logits[64];
  __shared__ float tmp[64];
  const int b = blockIdx.y, i = blockIdx.x, t = threadIdx.x;  // 64 threads
  const float* qrow = g_q + ((long)b*64 + i)*HW;
  for (int n=t;n<HW;n+=64) qs[n] = qrow[n];
  __syncthreads();
  for (int j=0;j<64;j++){
    const float* krow = g_k + ((long)b*64 + j)*HW;
    float s = 0.f;
    for (int n=t;n<HW;n+=64) s += qs[n]*krow[n];
#pragma unroll
    for (int off=16;off;off>>=1) s += __shfl_down_sync(0xffffffffu, s, off);
    if ((t&31)==0) red[t>>5] = s;
    __syncthreads();
    if (t==0) logits[j] = (red[0]+red[1]) * 0.015625f;
    __syncthreads();
  }
  float xv = logits[t];
  tmp[t] = xv; __syncthreads();
  for (int s2=32; s2; s2>>=1){ if (t<s2) tmp[t] = fmaxf(tmp[t], tmp[t+s2]); __syncthreads(); }
  float mx = tmp[0]; __syncthreads();
  float e = expf(xv - mx);
  tmp[t] = e; __syncthreads();
  for (int s2=32; s2; s2>>=1){ if (t<s2) tmp[t] += tmp[t+s2]; __syncthreads(); }
  g_attn[((long)b*64+i)*64 + t] = e / tmp[0];
}

// ---------------- apply attention ----------------
__global__ void __launch_bounds__(256) tg_apply(float* __restrict__ out)
{
  __shared__ float as[64*64];
  const int b = blockIdx.z, tt = blockIdx.y;
  const int n = blockIdx.x*256 + threadIdx.x;
  for (int i=threadIdx.x;i<4096;i+=256) as[i] = g_attn[(long)b*4096 + i];
  __syncthreads();
  float acc[64];
#pragma unroll
  for (int c=0;c<64;c++) acc[c]=0.f;
  const float* v = g_hs + (((long)b*TSTEPS + tt)*64)*HW + n;
  for (int d=0; d<64; d++){
    float vv = v[(long)d*HW];
#pragma unroll
    for (int c=0;c<64;c++) acc[c] += as[c*64+d]*vv;
  }
  float* op = out + (((long)b*TSTEPS + tt)*64)*HW + n;
#pragma unroll
  for (int c=0;c<64;c++) op[(long)c*HW] = acc[c];
}

// ---------------- orchestration ----------------
extern "C" void kernel_launch(void* const* d_in, const int* in_sizes, int n_in,
                              void* d_out, int out_size)
{
  (void)in_sizes; (void)n_in; (void)out_size;
  const float* x      = (const float*)d_in[0];
  const float* w_rzo0 = (const float*)d_in[1];
  const float* b_rzo0 = (const float*)d_in[2];
  const float* w_rz0  = (const float*)d_in[3];
  const float* b_rz0  = (const float*)d_in[4];
  const float* w_h0   = (const float*)d_in[5];
  const float* b_h0   = (const float*)d_in[6];
  const float* w_o0   = (const float*)d_in[7];
  const float* b_o0   = (const float*)d_in[8];
  const float* td_h0  = (const float*)d_in[9];
  const float* td_m0  = (const float*)d_in[10];
  const float* tg0    = (const float*)d_in[11];
  const float* w_rzo1 = (const float*)d_in[12];
  const float* b_rzo1 = (const float*)d_in[13];
  const float* w_rz1  = (const float*)d_in[14];
  const float* b_rz1  = (const float*)d_in[15];
  const float* w_h1   = (const float*)d_in[16];
  const float* b_h1   = (const float*)d_in[17];
  const float* w_o1   = (const float*)d_in[18];
  const float* b_o1   = (const float*)d_in[19];
  const float* td_h1  = (const float*)d_in[20];
  const float* td_m1  = (const float*)d_in[21];
  const float* tg1    = (const float*)d_in[22];

  float *p_h0,*p_c0,*p_c1,*p_m,*p_A,*p_Bm,*p_rc,*p_xm,*p_gcr,*p_gmr,*p_hs,*p_zero;
  cudaGetSymbolAddress((void**)&p_h0,  g_h0);
  cudaGetSymbolAddress((void**)&p_c0,  g_c0);
  cudaGetSymbolAddress((void**)&p_c1,  g_c1);
  cudaGetSymbolAddress((void**)&p_m,   g_m);
  cudaGetSymbolAddress((void**)&p_A,   g_A);
  cudaGetSymbolAddress((void**)&p_Bm,  g_Bm);
  cudaGetSymbolAddress((void**)&p_rc,  g_rc);
  cudaGetSymbolAddress((void**)&p_xm,  g_xm);
  cudaGetSymbolAddress((void**)&p_gcr, g_gcr);
  cudaGetSymbolAddress((void**)&p_gmr, g_gmr);
  cudaGetSymbolAddress((void**)&p_hs,  g_hs);
  cudaGetSymbolAddress((void**)&p_zero,g_zero);

  const long nbs = (long)CHW;

  tg_zero_states<<<NB/256, 256>>>();

  for (int t=0; t<TSTEPS; t++){
    // ---------- layer 0 (Cin = 16+64 = 80) ----------
    const float* xt = x + (long)t*16*HW;
    const long xbs = (long)TSTEPS*16*HW;
    // merged A(192oc, in1=h) + B(128oc, in1=m): 24 + 16 = 40 oc8-groups, 2 y-units
    tg_conv3x3<<<dim3(4,40,BATCH),128>>>(xt,16,xbs, p_h0,nbs, p_m,nbs,
        w_rzo0,b_rzo0,p_A,(long)192*HW, w_rz0,b_rz0,p_Bm,(long)128*HW, 24, 80, 2, 4);
    tg_gates<<<NB/256,256>>>(p_A,p_Bm, p_h0,nbs, p_c0, tg0, td_h0, td_m0);
    // merged gc(in1=rc) + gm(in1=xm), same weights w_h0: 8 + 8 groups, 1 y-unit
    tg_conv3x3<<<dim3(8,16,BATCH),128>>>(xt,16,xbs, p_rc,nbs, p_xm,nbs,
        w_h0,b_h0,p_gcr,nbs, w_h0,b_h0,p_gmr,nbs, 8, 80, 1, 8);
    tg_cm<<<NB/256,256>>>(p_c0);
    tg_conv1x1<<<dim3(8,BATCH,16),256>>>(p_c0, w_o0, b_o0, p_h0, nbs);

    // ---------- layer 1 (Cin = 64+64 = 128) ----------
    const float* h1p = (t==0) ? p_zero : (p_hs + (long)(t-1)*CHW);
    const long h1bs  = (t==0) ? nbs : (long)TSTEPS*CHW;
    tg_conv3x3<<<dim3(4,40,BATCH),128>>>(p_h0,64,nbs, h1p,h1bs, p_m,nbs,
        w_rzo1,b_rzo1,p_A,(long)192*HW, w_rz1,b_rz1,p_Bm,(long)128*HW, 24, 128, 2, 4);
    tg_gates<<<NB/256,256>>>(p_A,p_Bm, h1p,h1bs, p_c1, tg1, td_h1, td_m1);
    tg_conv3x3<<<dim3(8,16,BATCH),128>>>(p_h0,64,nbs, p_rc,nbs, p_xm,nbs,
        w_h1,b_h1,p_gcr,nbs, w_h1,b_h1,p_gmr,nbs, 8, 128, 1, 8);
    tg_cm<<<NB/256,256>>>(p_c1);
    tg_conv1x1<<<dim3(8,BATCH,16),256>>>(p_c1, w_o1, b_o1, p_hs + (long)t*CHW, (long)TSTEPS*CHW);
  }

  tg_qk<<<NB/256,256>>>();
  tg_attn<<<dim3(64,BATCH),64>>>();
  tg_apply<<<dim3(16,TSTEPS,BATCH),256>>>((float*)d_out);
}

// round 6
// speedup vs baseline: 2.5231x; 1.2444x over previous
#include <cuda_runtime.h>
#include <math.h>
#include <stdint.h>

#define BATCH 4
#define TSTEPS 8
#define HC 64
#define HW 4096
#define CHW (HC*HW)            // 262144
#define NB (BATCH*HC*HW)       // 1048576

typedef unsigned long long u64;

// ---------------- f32x2 packed helpers ----------------
__device__ __forceinline__ u64 pk2(float lo, float hi){
  u64 r; asm("mov.b64 %0, {%1,%2};" : "=l"(r) : "f"(lo), "f"(hi)); return r;
}
__device__ __forceinline__ u64 dup2(float v){
  u64 r; asm("mov.b64 %0, {%1,%1};" : "=l"(r) : "f"(v)); return r;
}
__device__ __forceinline__ void fma2(u64 &acc, u64 a, u64 b){
  asm("fma.rn.f32x2 %0, %1, %2, %0;" : "+l"(acc) : "l"(a), "l"(b));
}
__device__ __forceinline__ float2 upk(u64 v){
  float2 f; asm("mov.b64 {%0,%1}, %2;" : "=f"(f.x), "=f"(f.y) : "l"(v)); return f;
}
// ---------------- cp.async helpers ----------------
__device__ __forceinline__ void cpa4(uint32_t saddr, const float* g, int nbytes){
  asm volatile("cp.async.ca.shared.global [%0], [%1], 4, %2;"
               :: "r"(saddr), "l"(g), "r"(nbytes) : "memory");
}
__device__ __forceinline__ void cpcommit(){ asm volatile("cp.async.commit_group;" ::: "memory"); }
__device__ __forceinline__ void cpwait1(){ asm volatile("cp.async.wait_group 1;" ::: "memory"); }
__device__ __forceinline__ void cpwait0(){ asm volatile("cp.async.wait_group 0;" ::: "memory"); }

// ---------------- device scratch (static) ----------------
__device__ float g_h0[NB];
__device__ float g_c0[NB];
__device__ float g_c1[NB];
__device__ float g_m[NB];
__device__ float g_rc[NB], g_xm[NB];
__device__ float g_r[NB], g_z[NB], g_o[NB], g_xr[NB], g_xz[NB];
__device__ float g_gct[NB], g_gmt[NB];
__device__ float g_q[NB], g_k[NB];
__device__ float g_attn[BATCH*64*64];
__device__ float g_hs[BATCH*TSTEPS*HC*HW];
__device__ float g_zero[NB];   // NEVER written -> stays zero

__device__ __forceinline__ float sigf(float x){ return 1.f/(1.f+expf(-x)); }

__global__ void tg_zero_states(){
  int i = blockIdx.x*256 + threadIdx.x;
  if (i < NB){ g_h0[i]=0.f; g_c0[i]=0.f; g_c1[i]=0.f; g_m[i]=0.f; }
}

// ---------------- merged dual-stream 3x3 conv with FUSED pointwise epilogue ------
// Block 128 thr = 8 rows x 16 colgroups(4px). Each thread: 4 px x 8 oc (4 oc-pairs).
// Stream select: blockIdx.y < nA8 -> A, else B.
// mode 0 (gate conv, A=rzo 24 grp / B=rz 16 grp):
//   A seg0: r=sig(a*gate+h*dh)->g_r, rc=r*c->g_rc ; seg1: z->g_z ; seg2: o=sig(a)->g_o
//   B seg0: xr=sig(a*gate+m*dm)->g_xr, xm=xr*m->g_xm ; seg1: xz->g_xz
// mode 1 (candidate conv, A=gc 8 grp / B=gm 8 grp), fused cell update:
//   A: tc=tanh(a); c=z*c+(1-z)*tc (in place), g_gct=tc
//   B: tm=tanh(a); m=xz*m+(1-xz)*tm (in place), g_gmt=tm
#define CC 4
__global__ void __launch_bounds__(128,5) tg_conv3x3(
    const float* __restrict__ in0, int C0, long bs0,
    const float* __restrict__ in1A, long bs1A,
    const float* __restrict__ in1B, long bs1B,
    const float* __restrict__ wA, const float* __restrict__ bA,
    const float* __restrict__ wB, const float* __restrict__ bB,
    int nA8, int Cin, int mode,
    const float* __restrict__ hp, long hbs,
    float* __restrict__ cbuf,
    const float* __restrict__ tgp, const float* __restrict__ tdh,
    const float* __restrict__ tdm)
{
  __shared__ __align__(16) float tile[3][CC][720];   // 10 rows x 72 cols, px0 at col 4
  __shared__ __align__(16) u64   ws[2][CC][4][12];   // [pair][ky][kx(pad4)] oc-pair packed

  const int tid = threadIdx.x;
  const int b   = blockIdx.z;
  int ocb = blockIdx.y;
  const int ty = tid >> 4;          // 0..7
  const int tx = (tid & 15) * 4;    // 0..60
  const int y0 = blockIdx.x * 8;

  const int isA = (ocb < nA8);
  const float* in1; const float* w; const float* bias;
  long bs1;
  if (isA){ in1=in1A; bs1=bs1A; w=wA; bias=bA; }
  else { ocb-=nA8; in1=in1B; bs1=bs1B; w=wB; bias=bB; }

  const float* pin0 = in0 + (long)b*bs0;
  const float* pin1 = in1 + (long)b*bs1;

  // weight slot descriptors (144 u64 per chunk, 2 slots/thread)
  int wex[2], woff[2], wsts[2];
#pragma unroll
  for (int s=0;s<2;s++){
    int j = tid + s*128;
    wex[s] = (j < 144);
    int jj = wex[s] ? j : 0;
    int ci = jj/36; int rem = jj - ci*36; int p = rem/9; int k = rem - p*9;
    int oc0 = ocb*8 + 2*p;
    woff[s] = (oc0*Cin + ci)*9 + k;
    wsts[s] = (((ci*4)+p)*12 + (k/3)*4 + (k%3))*8;
  }
  const int nch = Cin/CC;
  const int wsBufBytes = CC*4*12*8;  // 1536
  char* wsb = (char*)&ws[0][0][0][0];
  uint32_t tbase = (uint32_t)__cvta_generic_to_shared(&tile[0][0][0]);

  // tile slot descriptors (6 slots covering 660 elems/cin)
  int soff[6], genc[6];
#pragma unroll
  for (int i=0;i<6;i++){
    int idx = tid + i*128;
    int ex = (idx < 660);
    int ii = ex ? idx : 0;
    int r = ii/66, c = ii - r*66;
    soff[i] = (r*72 + c + 3)*4;
    int gy = y0 + r - 1, gx = c - 1;
    int ok = ex && (gx>=0) && (gx<64) && (gy>=0) && (gy<64);
    genc[i] = ok ? (gy*64 + gx) : (ex ? -1 : -2);
  }

  u64 acc[4][4];
#pragma unroll
  for (int p=0;p<4;p++){
    u64 bb = pk2(bias[ocb*8+2*p], bias[ocb*8+2*p+1]);
#pragma unroll
    for (int px=0;px<4;px++) acc[p][px] = bb;
  }

  // ---- prologue ----
  float wh[2][2];
#pragma unroll
  for (int s=0;s<2;s++) if (wex[s]){   // chunk 0 weights: LDG + STS now
    float a0 = w[woff[s]];
    float a1 = w[woff[s] + Cin*9];
    *(u64*)(wsb + wsts[s]) = pk2(a0, a1);
  }
#pragma unroll
  for (int s=0;s<2;s++) if (wex[s]){   // chunk 1 weights: LDG, hold
    wh[s][0] = w[woff[s] + 9*CC];
    wh[s][1] = w[woff[s] + 9*CC + Cin*9];
  }
#pragma unroll 1
  for (int cc=0; cc<2; cc++){
#pragma unroll
    for (int ci=0;ci<CC;ci++){
      int cing = cc*CC + ci;
      const float* src = (cing < C0) ? pin0 + (long)cing*HW
                                     : pin1 + (long)(cing-C0)*HW;
      uint32_t sb = tbase + (uint32_t)((cc*CC + ci)*720*4);
#pragma unroll
      for (int i=0;i<6;i++)
        if (genc[i] != -2)
          cpa4(sb + soff[i], src + (genc[i]>=0 ? genc[i] : 0), genc[i]>=0 ? 4 : 0);
    }
    cpcommit();
  }

  // ---- main pipeline ----
  for (int c=0; c<nch; c++){
    if (c+1 < nch) cpwait1(); else cpwait0();
    __syncthreads();
    if (c+1 < nch){
#pragma unroll
      for (int s=0;s<2;s++) if (wex[s])
        *(u64*)(wsb + ((c+1)&1)*wsBufBytes + wsts[s]) = pk2(wh[s][0], wh[s][1]);
    }
    if (c+2 < nch){
#pragma unroll
      for (int s=0;s<2;s++) if (wex[s]){
        wh[s][0] = w[woff[s] + (c+2)*9*CC];
        wh[s][1] = w[woff[s] + (c+2)*9*CC + Cin*9];
      }
      int buf = (c+2)%3;
#pragma unroll
      for (int ci=0;ci<CC;ci++){
        int cing = (c+2)*CC + ci;
        const float* src = (cing < C0) ? pin0 + (long)cing*HW
                                       : pin1 + (long)(cing-C0)*HW;
        uint32_t sb = tbase + (uint32_t)((buf*CC + ci)*720*4);
#pragma unroll
        for (int i=0;i<6;i++)
          if (genc[i] != -2)
            cpa4(sb + soff[i], src + (genc[i]>=0 ? genc[i] : 0), genc[i]>=0 ? 4 : 0);
      }
      cpcommit();
    }
    // compute chunk c
    const int tb = c%3, wb = c&1;
#pragma unroll
    for (int ci=0;ci<CC;ci++){
#pragma unroll
      for (int r=0;r<3;r++){
        const float* row = &tile[tb][ci][(ty+r)*72 + tx + 3];
        float v0 = row[0];
        float4 vm = *reinterpret_cast<const float4*>(row+1);
        float v5 = row[5];
        u64 pv0=dup2(v0), pv1=dup2(vm.x), pv2=dup2(vm.y),
            pv3=dup2(vm.z), pv4=dup2(vm.w), pv5=dup2(v5);
#pragma unroll
        for (int p=0;p<4;p++){
          ulonglong2 w01 = *reinterpret_cast<const ulonglong2*>(&ws[wb][ci][p][r*4]);
          u64 w2 = ws[wb][ci][p][r*4+2];
          fma2(acc[p][0], w01.x, pv0); fma2(acc[p][0], w01.y, pv1); fma2(acc[p][0], w2, pv2);
          fma2(acc[p][1], w01.x, pv1); fma2(acc[p][1], w01.y, pv2); fma2(acc[p][1], w2, pv3);
          fma2(acc[p][2], w01.x, pv2); fma2(acc[p][2], w01.y, pv3); fma2(acc[p][2], w2, pv4);
          fma2(acc[p][3], w01.x, pv3); fma2(acc[p][3], w01.y, pv4); fma2(acc[p][3], w2, pv5);
        }
      }
    }
  }

  // ---- fused epilogue ----
  const long pixb = (long)(y0+ty)*64 + tx;
  const int seg = ocb >> 3;              // 8 oc per group, 64 per segment
#pragma unroll
  for (int p=0;p<4;p++){
    float2 a0=upk(acc[p][0]), a1=upk(acc[p][1]), a2=upk(acc[p][2]), a3=upk(acc[p][3]);
    float av[2][4] = {{a0.x,a1.x,a2.x,a3.x},{a0.y,a1.y,a2.y,a3.y}};
#pragma unroll
    for (int k=0;k<2;k++){
      int oc = ocb*8 + 2*p + k;
      int ch = oc & 63;
      long idx = (long)b*CHW + (long)ch*HW + pixb;
      if (mode == 0){
        if (isA){
          if (seg < 2){
            float gate = sigf(tgp[ch]);
            float dh = expf(-tdh[ch]);
            float4 hv = *reinterpret_cast<const float4*>(&hp[(long)b*hbs + (long)ch*HW + pixb]);
            float4 g;
            g.x = sigf(av[k][0]*gate + hv.x*dh);
            g.y = sigf(av[k][1]*gate + hv.y*dh);
            g.z = sigf(av[k][2]*gate + hv.z*dh);
            g.w = sigf(av[k][3]*gate + hv.w*dh);
            if (seg == 0){
              *reinterpret_cast<float4*>(&g_r[idx]) = g;
              float4 cv = *reinterpret_cast<const float4*>(&cbuf[idx]);
              float4 rc = make_float4(g.x*cv.x, g.y*cv.y, g.z*cv.z, g.w*cv.w);
              *reinterpret_cast<float4*>(&g_rc[idx]) = rc;
            } else {
              *reinterpret_cast<float4*>(&g_z[idx]) = g;
            }
          } else {
            float4 g = make_float4(sigf(av[k][0]), sigf(av[k][1]),
                                   sigf(av[k][2]), sigf(av[k][3]));
            *reinterpret_cast<float4*>(&g_o[idx]) = g;
          }
        } else {
          float gate = sigf(tgp[ch]);
          float dm = expf(-tdm[ch]);
          float4 mv = *reinterpret_cast<const float4*>(&g_m[idx]);
          float4 g;
          g.x = sigf(av[k][0]*gate + mv.x*dm);
          g.y = sigf(av[k][1]*gate + mv.y*dm);
          g.z = sigf(av[k][2]*gate + mv.z*dm);
          g.w = sigf(av[k][3]*gate + mv.w*dm);
          if (seg == 0){
            *reinterpret_cast<float4*>(&g_xr[idx]) = g;
            float4 xm = make_float4(g.x*mv.x, g.y*mv.y, g.z*mv.z, g.w*mv.w);
            *reinterpret_cast<float4*>(&g_xm[idx]) = xm;
          } else {
            *reinterpret_cast<float4*>(&g_xz[idx]) = g;
          }
        }
      } else {
        // mode 1: candidate conv + fused cell update
        float4 tc = make_float4(tanhf(av[k][0]), tanhf(av[k][1]),
                                tanhf(av[k][2]), tanhf(av[k][3]));
        if (isA){
          float4 zv = *reinterpret_cast<const float4*>(&g_z[idx]);
          float4 cv = *reinterpret_cast<const float4*>(&cbuf[idx]);
          float4 cn;
          cn.x = zv.x*cv.x + (1.f-zv.x)*tc.x;
          cn.y = zv.y*cv.y + (1.f-zv.y)*tc.y;
          cn.z = zv.z*cv.z + (1.f-zv.z)*tc.z;
          cn.w = zv.w*cv.w + (1.f-zv.w)*tc.w;
          *reinterpret_cast<float4*>(&cbuf[idx]) = cn;
          *reinterpret_cast<float4*>(&g_gct[idx]) = tc;
        } else {
          float4 xzv = *reinterpret_cast<const float4*>(&g_xz[idx]);
          float4 mv  = *reinterpret_cast<const float4*>(&g_m[idx]);
          float4 mn;
          mn.x = xzv.x*mv.x + (1.f-xzv.x)*tc.x;
          mn.y = xzv.y*mv.y + (1.f-xzv.y)*tc.y;
          mn.z = xzv.z*mv.z + (1.f-xzv.z)*tc.z;
          mn.w = xzv.w*mv.w + (1.f-xzv.w)*tc.w;
          *reinterpret_cast<float4*>(&g_m[idx]) = mn;
          *reinterpret_cast<float4*>(&g_gmt[idx]) = tc;
        }
      }
    }
  }
}

// ---------------- 1x1 conv (f32x2) with fused h = o*tanh(.) ----------------
__global__ void __launch_bounds__(256) tg_conv1x1(
    const float* __restrict__ c,
    const float* __restrict__ w, const float* __restrict__ bias,
    float* __restrict__ out, long bsOut)
{
  __shared__ u64 ws[4*128];
  const int tid = threadIdx.x;
  const int b   = blockIdx.y;
  const int ocg = blockIdx.z;   // group of 4 oc
  for (int i=tid;i<4*128;i+=256){
    float v = w[(long)(ocg*4)*128 + i];
    ws[i] = pk2(v,v);
  }
  __syncthreads();
  const int pix = (blockIdx.x*256 + tid)*2;
  u64 acc[4];
#pragma unroll
  for (int oc=0;oc<4;oc++){
    float bv = bias[ocg*4+oc];
    acc[oc] = pk2(bv,bv);
  }
  const long base = (long)b*CHW + pix;
  for (int cc=0;cc<64;cc++){
    u64 v0 = *reinterpret_cast<const u64*>(&c[base + (long)cc*HW]);
#pragma unroll
    for (int oc=0;oc<4;oc++) fma2(acc[oc], ws[oc*128+cc], v0);
  }
  for (int cc=0;cc<64;cc++){
    u64 v0 = *reinterpret_cast<const u64*>(&g_m[base + (long)cc*HW]);
#pragma unroll
    for (int oc=0;oc<4;oc++) fma2(acc[oc], ws[oc*128+64+cc], v0);
  }
#pragma unroll
  for (int oc=0;oc<4;oc++){
    int ocf = ocg*4+oc;
    float2 ov = *reinterpret_cast<const float2*>(&g_o[base + (long)ocf*HW]);
    float2 a = upk(acc[oc]);
    float2 res;
    res.x = ov.x * tanhf(a.x);
    res.y = ov.y * tanhf(a.y);
    *reinterpret_cast<float2*>(&out[(long)b*bsOut + (long)ocf*HW + pix]) = res;
  }
}

// ---------------- q/k from final-step last-layer gates ----------------
__global__ void tg_qk()
{
  int idx = blockIdx.x*256 + threadIdx.x;
  if (idx >= NB) return;
  float rv = g_r[idx], xrv = g_xr[idx];
  g_q[idx] = 0.25f*(rv + xrv + g_c1[idx] + g_gct[idx]);
  g_k[idx] = 0.25f*(rv + xrv + g_m[idx]  + g_gmt[idx]);
}

// ---------------- attention logits + softmax ----------------
__global__ void tg_attn()
{
  __shared__ float qs[HW];
  __shared__ float red[2];
  __shared__ float logits[64];
  __shared__ float tmp[64];
  const int b = blockIdx.y, i = blockIdx.x, t = threadIdx.x;  // 64 threads
  const float* qrow = g_q + ((long)b*64 + i)*HW;
  for (int n=t;n<HW;n+=64) qs[n] = qrow[n];
  __syncthreads();
  for (int j=0;j<64;j++){
    const float* krow = g_k + ((long)b*64 + j)*HW;
    float s = 0.f;
    for (int n=t;n<HW;n+=64) s += qs[n]*krow[n];
#pragma unroll
    for (int off=16;off;off>>=1) s += __shfl_down_sync(0xffffffffu, s, off);
    if ((t&31)==0) red[t>>5] = s;
    __syncthreads();
    if (t==0) logits[j] = (red[0]+red[1]) * 0.015625f;
    __syncthreads();
  }
  float xv = logits[t];
  tmp[t] = xv; __syncthreads();
  for (int s2=32; s2; s2>>=1){ if (t<s2) tmp[t] = fmaxf(tmp[t], tmp[t+s2]); __syncthreads(); }
  float mx = tmp[0]; __syncthreads();
  float e = expf(xv - mx);
  tmp[t] = e; __syncthreads();
  for (int s2=32; s2; s2>>=1){ if (t<s2) tmp[t] += tmp[t+s2]; __syncthreads(); }
  g_attn[((long)b*64+i)*64 + t] = e / tmp[0];
}

// ---------------- apply attention ----------------
__global__ void __launch_bounds__(256) tg_apply(float* __restrict__ out)
{
  __shared__ float as[64*64];
  const int b = blockIdx.z, tt = blockIdx.y;
  const int n = blockIdx.x*256 + threadIdx.x;
  for (int i=threadIdx.x;i<4096;i+=256) as[i] = g_attn[(long)b*4096 + i];
  __syncthreads();
  float acc[64];
#pragma unroll
  for (int c=0;c<64;c++) acc[c]=0.f;
  const float* v = g_hs + (((long)b*TSTEPS + tt)*64)*HW + n;
  for (int d=0; d<64; d++){
    float vv = v[(long)d*HW];
#pragma unroll
    for (int c=0;c<64;c++) acc[c] += as[c*64+d]*vv;
  }
  float* op = out + (((long)b*TSTEPS + tt)*64)*HW + n;
#pragma unroll
  for (int c=0;c<64;c++) op[(long)c*HW] = acc[c];
}

// ---------------- orchestration ----------------
extern "C" void kernel_launch(void* const* d_in, const int* in_sizes, int n_in,
                              void* d_out, int out_size)
{
  (void)in_sizes; (void)n_in; (void)out_size;
  const float* x      = (const float*)d_in[0];
  const float* w_rzo0 = (const float*)d_in[1];
  const float* b_rzo0 = (const float*)d_in[2];
  const float* w_rz0  = (const float*)d_in[3];
  const float* b_rz0  = (const float*)d_in[4];
  const float* w_h0   = (const float*)d_in[5];
  const float* b_h0   = (const float*)d_in[6];
  const float* w_o0   = (const float*)d_in[7];
  const float* b_o0   = (const float*)d_in[8];
  const float* td_h0  = (const float*)d_in[9];
  const float* td_m0  = (const float*)d_in[10];
  const float* tg0    = (const float*)d_in[11];
  const float* w_rzo1 = (const float*)d_in[12];
  const float* b_rzo1 = (const float*)d_in[13];
  const float* w_rz1  = (const float*)d_in[14];
  const float* b_rz1  = (const float*)d_in[15];
  const float* w_h1   = (const float*)d_in[16];
  const float* b_h1   = (const float*)d_in[17];
  const float* w_o1   = (const float*)d_in[18];
  const float* b_o1   = (const float*)d_in[19];
  const float* td_h1  = (const float*)d_in[20];
  const float* td_m1  = (const float*)d_in[21];
  const float* tg1    = (const float*)d_in[22];

  float *p_h0,*p_c0,*p_c1,*p_m,*p_rc,*p_xm,*p_hs,*p_zero;
  cudaGetSymbolAddress((void**)&p_h0,  g_h0);
  cudaGetSymbolAddress((void**)&p_c0,  g_c0);
  cudaGetSymbolAddress((void**)&p_c1,  g_c1);
  cudaGetSymbolAddress((void**)&p_m,   g_m);
  cudaGetSymbolAddress((void**)&p_rc,  g_rc);
  cudaGetSymbolAddress((void**)&p_xm,  g_xm);
  cudaGetSymbolAddress((void**)&p_hs,  g_hs);
  cudaGetSymbolAddress((void**)&p_zero,g_zero);

  const long nbs = (long)CHW;

  tg_zero_states<<<NB/256, 256>>>();

  for (int t=0; t<TSTEPS; t++){
    // ---------- layer 0 (Cin = 16+64 = 80) ----------
    const float* xt = x + (long)t*16*HW;
    const long xbs = (long)TSTEPS*16*HW;
    // gate conv: A=rzo(24 grp, in1=h0) + B=rz(16 grp, in1=m), fused gate epilogue
    tg_conv3x3<<<dim3(8,40,BATCH),128>>>(xt,16,xbs, p_h0,nbs, p_m,nbs,
        w_rzo0,b_rzo0, w_rz0,b_rz0, 24, 80, 0, p_h0,nbs, p_c0, tg0, td_h0, td_m0);
    // candidate conv: A=gc(in1=rc) + B=gm(in1=xm), same weights, fused cell update
    tg_conv3x3<<<dim3(8,16,BATCH),128>>>(xt,16,xbs, p_rc,nbs, p_xm,nbs,
        w_h0,b_h0, w_h0,b_h0, 8, 80, 1, p_zero,nbs, p_c0, tg0, td_h0, td_m0);
    tg_conv1x1<<<dim3(8,BATCH,16),256>>>(p_c0, w_o0, b_o0, p_h0, nbs);

    // ---------- layer 1 (Cin = 64+64 = 128) ----------
    const float* h1p = (t==0) ? p_zero : (p_hs + (long)(t-1)*CHW);
    const long h1bs  = (t==0) ? nbs : (long)TSTEPS*CHW;
    tg_conv3x3<<<dim3(8,40,BATCH),128>>>(p_h0,64,nbs, h1p,h1bs, p_m,nbs,
        w_rzo1,b_rzo1, w_rz1,b_rz1, 24, 128, 0, h1p,h1bs, p_c1, tg1, td_h1, td_m1);
    tg_conv3x3<<<dim3(8,16,BATCH),128>>>(p_h0,64,nbs, p_rc,nbs, p_xm,nbs,
        w_h1,b_h1, w_h1,b_h1, 8, 128, 1, p_zero,nbs, p_c1, tg1, td_h1, td_m1);
    tg_conv1x1<<<dim3(8,BATCH,16),256>>>(p_c1, w_o1, b_o1, p_hs + (long)t*CHW, (long)TSTEPS*CHW);
  }

  tg_qk<<<NB/256,256>>>();
  tg_attn<<<dim3(64,BATCH),64>>>();
  tg_apply<<<dim3(16,TSTEPS,BATCH),256>>>((float*)d_out);
}